// round 14
// baseline (speedup 1.0000x reference)
#include <cuda_runtime.h>
#include <cuda_bf16.h>
#include <math.h>

// Problem constants (B=1, D=16, H=64, W=64)
#define NTOK   65536
#define CDIM   192
#define NHEADS 6
#define HD     32
#define HIDDEN 768
#define RANK1  384
#define RANK2  96
#define ATTN_SCALE 0.17677669529663687f  // 32^-0.5

typedef __nv_bfloat16 bf16;

// ---------------- scratch (device globals; no runtime allocation) ----------------
__device__ bf16  g_ln[(size_t)NTOK * CDIM];
__device__ bf16  g_qkv[(size_t)NTOK * 576];
__device__ bf16  g_attn[(size_t)NTOK * CDIM];
__device__ float g_x1[(size_t)NTOK * CDIM];
__device__ bf16  g_r1[(size_t)NTOK * RANK1];
__device__ bf16  g_hid[(size_t)NTOK * HIDDEN];
__device__ bf16  g_conv[(size_t)NTOK * HIDDEN];
__device__ bf16  g_r2[(size_t)NTOK * 128];      // padded K (cols 96..127 = 0)
__device__ bf16  g_btab[6 * 65536];             // per-head rel-bias table [h][r][c]
// transposed bf16 weights [N][K]
__device__ bf16  g_qkvwt[576 * 192];
__device__ bf16  g_projwt[192 * 192];
__device__ bf16  g_fc1At[RANK1 * 192];
__device__ bf16  g_fc1Bt[HIDDEN * RANK1];
__device__ bf16  g_fc2At[128 * HIDDEN];         // padded N rows 96..127 = 0
__device__ bf16  g_fc2Bt[CDIM * 128];           // padded K cols 96..127 = 0

// ---------------- helpers ----------------
__device__ __forceinline__ int token_to_wrow(int n) {
    int w = n & 63, h = (n >> 6) & 63, d = n >> 12;
    int win = ((d >> 2) << 6) | ((h >> 3) << 3) | (w >> 3);
    int t   = ((d & 3) << 6) | ((h & 7) << 3) | (w & 7);
    return (win << 8) | t;
}
__device__ __forceinline__ int wrow_to_token(int r) {
    int win = r >> 8, t = r & 255;
    int d = ((win >> 6) << 2) | (t >> 6);
    int h = (((win >> 3) & 7) << 3) | ((t >> 3) & 7);
    int w = ((win & 7) << 3) | (t & 7);
    return (d << 12) | (h << 6) | w;
}
__device__ __forceinline__ void cp16(void* smem, const void* gmem) {
    unsigned s = (unsigned)__cvta_generic_to_shared(smem);
    asm volatile("cp.async.cg.shared.global [%0], [%1], 16;\n" :: "r"(s), "l"(gmem));
}
__device__ __forceinline__ void cp16z(void* smem, const void* gmem) {
    unsigned s = (unsigned)__cvta_generic_to_shared(smem);
    asm volatile("cp.async.cg.shared.global [%0], [%1], 16, 0;\n" :: "r"(s), "l"(gmem));
}
__device__ __forceinline__ void ldsm4(unsigned* r, unsigned addr) {
    asm volatile("ldmatrix.sync.aligned.m8n8.x4.shared.b16 {%0,%1,%2,%3}, [%4];"
                 : "=r"(r[0]), "=r"(r[1]), "=r"(r[2]), "=r"(r[3]) : "r"(addr));
}
#define MMA_BF16(C, A, B)                                                      \
    asm volatile(                                                              \
        "mma.sync.aligned.m16n8k16.row.col.f32.bf16.bf16.f32 "                 \
        "{%0,%1,%2,%3},{%4,%5,%6,%7},{%8,%9},{%0,%1,%2,%3};\n"                 \
        : "+f"((C)[0]), "+f"((C)[1]), "+f"((C)[2]), "+f"((C)[3])               \
        : "r"((A)[0]), "r"((A)[1]), "r"((A)[2]), "r"((A)[3]),                  \
          "r"((B)[0]), "r"((B)[1]))

// ---------------- all-weights convert + transpose (one launch, with padding) -------
__global__ void wconv_all(const float* s0, const float* s1, const float* s2,
                          const float* s3, const float* s4, const float* s5,
                          bf16* d0, bf16* d1, bf16* d2,
                          bf16* d3, bf16* d4, bf16* d5) {
    int idx = blockIdx.x * 256 + threadIdx.x;
    if (idx < 110592) {                 // qkv [192][576] -> [576][192]
        int k = idx / 576, n = idx - k * 576;
        d0[n * 192 + k] = __float2bfloat16(s0[idx]);
    } else if (idx < 147456) {          // proj [192][192] -> [192][192]
        idx -= 110592;
        int k = idx / 192, n = idx - k * 192;
        d1[n * 192 + k] = __float2bfloat16(s1[idx]);
    } else if (idx < 221184) {          // fc1A [192][384] -> [384][192]
        idx -= 147456;
        int k = idx / 384, n = idx - k * 384;
        d2[n * 192 + k] = __float2bfloat16(s2[idx]);
    } else if (idx < 516096) {          // fc1B [384][768] -> [768][384]
        idx -= 221184;
        int k = idx / 768, n = idx - k * 768;
        d3[n * 384 + k] = __float2bfloat16(s3[idx]);
    } else if (idx < 614400) {          // fc2A [768][96] -> [128][768] (pad n)
        idx -= 516096;
        int n = idx / 768, k = idx - n * 768;
        d4[idx] = (n < 96) ? __float2bfloat16(s4[k * 96 + n]) : __float2bfloat16(0.f);
    } else if (idx < 638976) {          // fc2B [96][192] -> [192][128] (pad k)
        idx -= 614400;
        int n = idx / 128, k = idx - n * 128;
        d5[idx] = (k < 96) ? __float2bfloat16(s5[k * 192 + n]) : __float2bfloat16(0.f);
    }
}

// ---------------- rel-bias table: btab[h][r][c] = rel_bias[relidx(r,c)][h] --------
__global__ void btab_kernel(const float* __restrict__ rel_bias, bf16* __restrict__ bt) {
    int idx = blockIdx.x * 256 + threadIdx.x;   // 6*65536
    int h = idx >> 16, rc = idx & 65535;
    int r = rc >> 8, c = rc & 255;
    int ridx = ((r >> 6) - (c >> 6) + 3) * 225 +
               (((r >> 3) & 7) - ((c >> 3) & 7) + 7) * 15 +
               ((r & 7) - (c & 7) + 7);
    bt[idx] = __float2bfloat16(rel_bias[ridx * 6 + h]);
}

// ---------------- LayerNorm: warp per token -> bf16 out ----------------
template <bool PERM>
__global__ void __launch_bounds__(256)
ln_kernel(const float* __restrict__ x, const float* __restrict__ g,
          const float* __restrict__ b, bf16* __restrict__ out) {
    int lane = threadIdx.x & 31, wid = threadIdx.x >> 5;
    int n = (blockIdx.x << 3) + wid;
    const float* xp = x + (size_t)n * CDIM;
    float v[6];
#pragma unroll
    for (int i = 0; i < 6; i++) v[i] = xp[lane + (i << 5)];
    float s = 0.f, s2 = 0.f;
#pragma unroll
    for (int i = 0; i < 6; i++) { s += v[i]; s2 += v[i] * v[i]; }
#pragma unroll
    for (int o = 16; o; o >>= 1) {
        s  += __shfl_xor_sync(0xffffffffu, s,  o);
        s2 += __shfl_xor_sync(0xffffffffu, s2, o);
    }
    float mean = s * (1.0f / CDIM);
    float rstd = rsqrtf(s2 * (1.0f / CDIM) - mean * mean + 1e-5f);
    int orow = PERM ? token_to_wrow(n) : n;
    bf16* op = out + (size_t)orow * CDIM;
#pragma unroll
    for (int i = 0; i < 6; i++) {
        int c = lane + (i << 5);
        op[c] = __float2bfloat16((v[i] - mean) * rstd * __ldg(g + c) + __ldg(b + c));
    }
}

// ---------------- BF16 GEMM 128x128x64, 2-stage, ldmatrix (R11 exact) --------------
#define GEMM_SMEM_BYTES (2 * 2 * 128 * 72 * 2)
#define ST_STRIDE (128 * 72)     // halves per stage per array
template <int MODE, bool OUTBF>
__global__ void __launch_bounds__(256)
mma_gemm(const bf16* __restrict__ A, const bf16* __restrict__ B,
         const float* __restrict__ bias, const float* __restrict__ resid,
         void* __restrict__ Cv, int N, int K) {
    extern __shared__ bf16 gsm[];
    bf16* As = gsm;                       // [2][128][72]
    bf16* Bs = gsm + 2 * ST_STRIDE;       // [2][128][72]
    int tid = threadIdx.x, lane = tid & 31, warp = tid >> 5;
    int wm = warp & 1, wn = warp >> 1;
    int bm = blockIdx.y << 7, bn = blockIdx.x << 7;
    int q = lane & 3, g8 = lane >> 2;

    float c[4][4][4];
#pragma unroll
    for (int mt = 0; mt < 4; mt++)
#pragma unroll
        for (int nt = 0; nt < 4; nt++)
#pragma unroll
            for (int r = 0; r < 4; r++) c[mt][nt][r] = 0.f;

    int KT = K >> 6;

    unsigned asm_base = (unsigned)__cvta_generic_to_shared(As);
    unsigned bsm_base = (unsigned)__cvta_generic_to_shared(Bs);
    int lrow = lane & 15, lcol = (lane >> 4) << 3;
    unsigned a_off = ((wm * 64 + lrow) * 72 + lcol) * 2;
    unsigned b_off = ((wn * 32 + lrow) * 72 + lcol) * 2;

#define COPY_STAGE(S, K0)                                                         \
    do {                                                                          \
        _Pragma("unroll")                                                         \
        for (int cc = 0; cc < 4; cc++) {                                          \
            int id = tid + (cc << 8);                                             \
            int r = id >> 3, o = (id & 7) << 3;                                   \
            cp16(&As[(S) * ST_STRIDE + r * 72 + o],                               \
                 A + (size_t)(bm + r) * K + (K0) + o);                            \
            if (bn + r < N)                                                       \
                cp16(&Bs[(S) * ST_STRIDE + r * 72 + o],                           \
                     B + (size_t)(bn + r) * K + (K0) + o);                        \
            else                                                                  \
                cp16z(&Bs[(S) * ST_STRIDE + r * 72 + o], B);                      \
        }                                                                         \
    } while (0)

    COPY_STAGE(0, 0);
    asm volatile("cp.async.commit_group;\n");

    for (int kt = 0; kt < KT; kt++) {
        asm volatile("cp.async.wait_group 0;\n");
        __syncthreads();
        if (kt + 1 < KT) COPY_STAGE((kt + 1) & 1, (kt + 1) << 6);
        asm volatile("cp.async.commit_group;\n");
        int s = kt & 1;
        unsigned aS = asm_base + s * (ST_STRIDE * 2) + a_off;
        unsigned bS = bsm_base + s * (ST_STRIDE * 2) + b_off;
#pragma unroll
        for (int kk = 0; kk < 64; kk += 16) {
            unsigned af[4][4], bf[4][4];
#pragma unroll
            for (int mt = 0; mt < 4; mt++)
                ldsm4(af[mt], aS + (mt * 16 * 72 + kk) * 2);
#pragma unroll
            for (int ntp = 0; ntp < 2; ntp++)
                ldsm4(bf[ntp * 2], bS + (ntp * 16 * 72 + kk) * 2);
#pragma unroll
            for (int mt = 0; mt < 4; mt++)
#pragma unroll
                for (int ntp = 0; ntp < 2; ntp++) {
                    unsigned b0[2] = { bf[ntp * 2][0], bf[ntp * 2][2] };
                    unsigned b1[2] = { bf[ntp * 2][1], bf[ntp * 2][3] };
                    MMA_BF16(c[mt][ntp * 2 + 0], af[mt], b0);
                    MMA_BF16(c[mt][ntp * 2 + 1], af[mt], b1);
                }
        }
    }
#undef COPY_STAGE

#pragma unroll
    for (int mt = 0; mt < 4; mt++) {
        int row0 = bm + wm * 64 + mt * 16 + g8;
#pragma unroll
        for (int half = 0; half < 2; half++) {
            int row = row0 + half * 8;
            int orow = (MODE == 2) ? wrow_to_token(row) : row;
#pragma unroll
            for (int nt = 0; nt < 4; nt++) {
                int col = bn + wn * 32 + nt * 8 + (q << 1);
                if (col < N) {
                    float v0 = c[mt][nt][half * 2 + 0];
                    float v1 = c[mt][nt][half * 2 + 1];
                    if (MODE >= 1) { v0 += bias[col]; v1 += bias[col + 1]; }
                    if (MODE >= 2) {
                        float2 rr = *(const float2*)(resid + (size_t)orow * N + col);
                        v0 += rr.x; v1 += rr.y;
                    }
                    if (OUTBF) {
                        *( __nv_bfloat162*)((bf16*)Cv + (size_t)orow * N + col) =
                            __floats2bfloat162_rn(v0, v1);
                    } else {
                        *(float2*)((float*)Cv + (size_t)orow * N + col) =
                            make_float2(v0, v1);
                    }
                }
            }
        }
    }
}

// ---------------- bf16 tensor-core windowed attention (bias table) -----------------
// smem: Ks 20480 | Vt 16896 | Ps 20480 | sid 1024  = 58880
#define ATTN_SMEM_BYTES 58880
__global__ void __launch_bounds__(256)
attn_mma_kernel(const bf16* __restrict__ qkv, const bf16* __restrict__ btab,
                bf16* __restrict__ out) {
    extern __shared__ char smc[];
    bf16*  Ks  = (bf16*)smc;             // [256][40]
    bf16*  Vt  = (bf16*)(smc + 20480);   // [32][264]
    bf16*  Ps  = (bf16*)(smc + 37376);   // [256][40]  (Q staging, then P)
    int*   sid = (int*)(smc + 57856);    // [256]

    int head = blockIdx.x, win = blockIdx.y;
    int tid = threadIdx.x, lane = tid & 31, warp = tid >> 5;
    int q = lane & 3, g8 = lane >> 2;
    int m0 = warp << 5;

    const bf16* base = qkv + (size_t)win * 256 * 576 + head * HD;
    for (int idx = tid; idx < 256 * 32; idx += 256) {
        int r = idx >> 5, d = idx & 31;
        const bf16* p = base + (size_t)r * 576 + d;
        Ks[r * 40 + d]  = p[192];
        Vt[d * 264 + r] = p[384];
    }
#pragma unroll 4
    for (int i = 0; i < 32; i++)
        Ps[(m0 + i) * 40 + lane] = base[(size_t)(m0 + i) * 576 + lane];
    {
        int t = tid;
        int gd = ((win >> 6) << 2) | (t >> 6);
        int gh = (((win >> 3) & 7) << 3) | ((t >> 3) & 7);
        int gw = ((win & 7) << 3) | (t & 7);
        sid[t] = ((((gd + 2) & 15) >> 2) << 6) | ((((gh + 4) & 63) >> 3) << 3) |
                 (((gw + 4) & 63) >> 3);
    }
    __syncthreads();

    unsigned qf[2][2][4];
#pragma unroll
    for (int mt = 0; mt < 2; mt++)
#pragma unroll
        for (int ks = 0; ks < 2; ks++) {
            int m = m0 + mt * 16 + g8, k = ks * 16 + 2 * q;
            qf[mt][ks][0] = *(const unsigned*)&Ps[m * 40 + k];
            qf[mt][ks][1] = *(const unsigned*)&Ps[(m + 8) * 40 + k];
            qf[mt][ks][2] = *(const unsigned*)&Ps[m * 40 + k + 8];
            qf[mt][ks][3] = *(const unsigned*)&Ps[(m + 8) * 40 + k + 8];
        }
    const bf16* btr[2][2];
    int msid[2][2];
#pragma unroll
    for (int mt = 0; mt < 2; mt++)
#pragma unroll
        for (int h = 0; h < 2; h++) {
            int r = m0 + mt * 16 + h * 8 + g8;
            btr[mt][h] = btab + (head << 16) + (r << 8);
            msid[mt][h] = sid[r];
        }
    __syncwarp();

    float o[2][4][4];
#pragma unroll
    for (int mt = 0; mt < 2; mt++)
#pragma unroll
        for (int nt = 0; nt < 4; nt++)
#pragma unroll
            for (int e = 0; e < 4; e++) o[mt][nt][e] = 0.f;
    float rs[2][2] = {{0.f, 0.f}, {0.f, 0.f}};

    for (int ck = 0; ck < 256; ck += 32) {
        float s[2][4][4];
#pragma unroll
        for (int mt = 0; mt < 2; mt++)
#pragma unroll
            for (int nt = 0; nt < 4; nt++)
#pragma unroll
                for (int e = 0; e < 4; e++) s[mt][nt][e] = 0.f;
#pragma unroll
        for (int ks = 0; ks < 2; ks++) {
            unsigned kf[4][2];
#pragma unroll
            for (int nt = 0; nt < 4; nt++) {
                int n = ck + nt * 8 + g8;
                kf[nt][0] = *(const unsigned*)&Ks[n * 40 + ks * 16 + 2 * q];
                kf[nt][1] = *(const unsigned*)&Ks[n * 40 + ks * 16 + 2 * q + 8];
            }
#pragma unroll
            for (int mt = 0; mt < 2; mt++)
#pragma unroll
                for (int nt = 0; nt < 4; nt++)
                    MMA_BF16(s[mt][nt], qf[mt][ks], kf[nt]);
        }
#pragma unroll
        for (int nt = 0; nt < 4; nt++) {
            int cc = ck + nt * 8;
            int c0 = cc + (q << 1);
            int sc = (q >= 2) ? sid[cc + 4] : sid[cc];
#pragma unroll
            for (int mt = 0; mt < 2; mt++)
#pragma unroll
                for (int h = 0; h < 2; h++) {
                    float p0, p1;
                    if (msid[mt][h] == sc) {
                        __nv_bfloat162 bb = *(const __nv_bfloat162*)(btr[mt][h] + c0);
                        p0 = __expf(fmaf(s[mt][nt][h * 2 + 0], ATTN_SCALE,
                                         __bfloat162float(bb.x)));
                        p1 = __expf(fmaf(s[mt][nt][h * 2 + 1], ATTN_SCALE,
                                         __bfloat162float(bb.y)));
                    } else { p0 = 0.f; p1 = 0.f; }
                    __nv_bfloat162 pp = __floats2bfloat162_rn(p0, p1);
                    rs[mt][h] += __bfloat162float(pp.x) + __bfloat162float(pp.y);
                    int r = m0 + mt * 16 + h * 8 + g8;
                    *(__nv_bfloat162*)&Ps[r * 40 + nt * 8 + (q << 1)] = pp;
                }
        }
        __syncwarp();
#pragma unroll
        for (int ks = 0; ks < 2; ks++) {
            unsigned vf[4][2], pf[2][4];
#pragma unroll
            for (int nto = 0; nto < 4; nto++) {
                int d = nto * 8 + g8;
                vf[nto][0] = *(const unsigned*)&Vt[d * 264 + ck + ks * 16 + 2 * q];
                vf[nto][1] = *(const unsigned*)&Vt[d * 264 + ck + ks * 16 + 2 * q + 8];
            }
#pragma unroll
            for (int mt = 0; mt < 2; mt++) {
                int m = m0 + mt * 16 + g8, k = ks * 16 + 2 * q;
                pf[mt][0] = *(const unsigned*)&Ps[m * 40 + k];
                pf[mt][1] = *(const unsigned*)&Ps[(m + 8) * 40 + k];
                pf[mt][2] = *(const unsigned*)&Ps[m * 40 + k + 8];
                pf[mt][3] = *(const unsigned*)&Ps[(m + 8) * 40 + k + 8];
            }
#pragma unroll
            for (int mt = 0; mt < 2; mt++)
#pragma unroll
                for (int nto = 0; nto < 4; nto++)
                    MMA_BF16(o[mt][nto], pf[mt], vf[nto]);
        }
        __syncwarp();
    }

#pragma unroll
    for (int mt = 0; mt < 2; mt++)
#pragma unroll
        for (int h = 0; h < 2; h++) {
            float v = rs[mt][h];
            v += __shfl_xor_sync(0xffffffffu, v, 1);
            v += __shfl_xor_sync(0xffffffffu, v, 2);
            rs[mt][h] = 1.f / v;
        }
#pragma unroll
    for (int mt = 0; mt < 2; mt++)
#pragma unroll
        for (int h = 0; h < 2; h++) {
            int r = m0 + mt * 16 + h * 8 + g8;
            bf16* op = out + (size_t)(win * 256 + r) * CDIM + head * HD;
            float inv = rs[mt][h];
#pragma unroll
            for (int nto = 0; nto < 4; nto++)
                *(__nv_bfloat162*)(op + nto * 8 + (q << 1)) =
                    __floats2bfloat162_rn(o[mt][nto][h * 2 + 0] * inv,
                                          o[mt][nto][h * 2 + 1] * inv);
        }
}

// ---------------- tiled depthwise 3x3x3 conv + bias + exact GELU -------------------
// stencil register-reuse: per (td,th,kd,kh) load 6 halo values for 12 FMAs
#define CONV_SMEM_BYTES (216 * 128 * 2)
__global__ void __launch_bounds__(256)
conv_gelu_tiled(const bf16* __restrict__ hin, const float* __restrict__ wt,
                const float* __restrict__ cb, bf16* __restrict__ hout) {
    extern __shared__ bf16 hs[];   // [216][128]
    int cg = blockIdx.x;
    int tile = blockIdx.y;
    int d0 = (tile >> 8) << 2;
    int h0 = ((tile >> 4) & 15) << 2;
    int w0 = (tile & 15) << 2;
    int tid = threadIdx.x;
    int c = tid & 127;
    int phalf = tid >> 7;
    int cbase = cg << 7;

#pragma unroll 4
    for (int i = 0; i < 108; i++) {
        int p = phalf + (i << 1);
        int pd = p / 36, rem = p - pd * 36;
        int ph = rem / 6, pw = rem - ph * 6;
        int gd = d0 - 1 + pd, gh = h0 - 1 + ph, gw = w0 - 1 + pw;
        bf16 v = __float2bfloat16(0.f);
        if ((unsigned)gd < 16u && (unsigned)gh < 64u && (unsigned)gw < 64u)
            v = hin[(size_t)((gd << 12) | (gh << 6) | gw) * HIDDEN + cbase + c];
        hs[p * 128 + c] = v;
    }
    float w[27];
#pragma unroll
    for (int k = 0; k < 27; k++) w[k] = wt[(cbase + c) * 27 + k];
    float bias = cb[cbase + c];
    __syncthreads();

    int tdb = phalf << 1;   // this thread covers td in {tdb, tdb+1}
#pragma unroll
    for (int tdh = 0; tdh < 8; tdh++) {
        int td = tdb + (tdh >> 2), th = tdh & 3;
        float acc[4];
        acc[0] = acc[1] = acc[2] = acc[3] = bias;
#pragma unroll
        for (int kd = 0; kd < 3; kd++)
#pragma unroll
            for (int kh = 0; kh < 3; kh++) {
                int pbase = (td + kd) * 36 + (th + kh) * 6;
                float v[6];
#pragma unroll
                for (int j = 0; j < 6; j++)
                    v[j] = __bfloat162float(hs[(pbase + j) * 128 + c]);
                const float* wk = w + (kd * 3 + kh) * 3;
#pragma unroll
                for (int tw = 0; tw < 4; tw++)
                    acc[tw] += wk[0] * v[tw] + wk[1] * v[tw + 1] + wk[2] * v[tw + 2];
            }
        int nb = ((d0 + td) << 12) | ((h0 + th) << 6) | w0;
#pragma unroll
        for (int tw = 0; tw < 4; tw++) {
            float a = acc[tw];
            float gl = 0.5f * a * (1.f + erff(a * 0.70710678118654752f));
            hout[(size_t)(nb + tw) * HIDDEN + cbase + c] = __float2bfloat16(gl);
        }
    }
}

// ---------------- launch ----------------
extern "C" void kernel_launch(void* const* d_in, const int* in_sizes, int n_in,
                              void* d_out, int out_size) {
    const float* x     = (const float*)d_in[0];
    const float* n1g   = (const float*)d_in[1];
    const float* n1b   = (const float*)d_in[2];
    const float* qkvw  = (const float*)d_in[3];
    const float* qkvb  = (const float*)d_in[4];
    const float* relb  = (const float*)d_in[5];
    const float* projw = (const float*)d_in[6];
    const float* projb = (const float*)d_in[7];
    const float* n2g   = (const float*)d_in[8];
    const float* n2b   = (const float*)d_in[9];
    const float* fc1A  = (const float*)d_in[10];
    const float* fc1Bw = (const float*)d_in[11];
    const float* fc1Bb = (const float*)d_in[12];
    const float* dww   = (const float*)d_in[13];
    const float* dwb   = (const float*)d_in[14];
    const float* fc2A  = (const float*)d_in[15];
    const float* fc2Bw = (const float*)d_in[16];
    const float* fc2Bb = (const float*)d_in[17];
    float* out = (float*)d_out;

    bf16 *p_ln, *p_qkv, *p_attn, *p_r1, *p_hid, *p_conv, *p_r2, *p_btab;
    bf16 *p_qkvwt, *p_projwt, *p_fc1At, *p_fc1Bt, *p_fc2At, *p_fc2Bt;
    float *p_x1;
    cudaGetSymbolAddress((void**)&p_ln,    g_ln);
    cudaGetSymbolAddress((void**)&p_qkv,   g_qkv);
    cudaGetSymbolAddress((void**)&p_attn,  g_attn);
    cudaGetSymbolAddress((void**)&p_x1,    g_x1);
    cudaGetSymbolAddress((void**)&p_r1,    g_r1);
    cudaGetSymbolAddress((void**)&p_hid,   g_hid);
    cudaGetSymbolAddress((void**)&p_conv,  g_conv);
    cudaGetSymbolAddress((void**)&p_r2,    g_r2);
    cudaGetSymbolAddress((void**)&p_btab,  g_btab);
    cudaGetSymbolAddress((void**)&p_qkvwt, g_qkvwt);
    cudaGetSymbolAddress((void**)&p_projwt, g_projwt);
    cudaGetSymbolAddress((void**)&p_fc1At, g_fc1At);
    cudaGetSymbolAddress((void**)&p_fc1Bt, g_fc1Bt);
    cudaGetSymbolAddress((void**)&p_fc2At, g_fc2At);
    cudaGetSymbolAddress((void**)&p_fc2Bt, g_fc2Bt);

    cudaFuncSetAttribute(attn_mma_kernel, cudaFuncAttributeMaxDynamicSharedMemorySize,
                         ATTN_SMEM_BYTES);
    cudaFuncSetAttribute(conv_gelu_tiled, cudaFuncAttributeMaxDynamicSharedMemorySize,
                         CONV_SMEM_BYTES);
    cudaFuncSetAttribute(mma_gemm<0, true>,  cudaFuncAttributeMaxDynamicSharedMemorySize, GEMM_SMEM_BYTES);
    cudaFuncSetAttribute(mma_gemm<1, true>,  cudaFuncAttributeMaxDynamicSharedMemorySize, GEMM_SMEM_BYTES);
    cudaFuncSetAttribute(mma_gemm<2, false>, cudaFuncAttributeMaxDynamicSharedMemorySize, GEMM_SMEM_BYTES);
    cudaFuncSetAttribute(mma_gemm<3, false>, cudaFuncAttributeMaxDynamicSharedMemorySize, GEMM_SMEM_BYTES);

    // 0. all weights convert+transpose + bias table
    wconv_all<<<(638976 + 255) / 256, 256>>>(qkvw, projw, fc1A, fc1Bw, fc2A, fc2Bw,
                                             p_qkvwt, p_projwt, p_fc1At, p_fc1Bt,
                                             p_fc2At, p_fc2Bt);
    btab_kernel<<<(6 * 65536) / 256, 256>>>(relb, p_btab);

    // 1. LN1 + window permute (bf16 out)
    ln_kernel<true><<<NTOK / 8, 256>>>(x, n1g, n1b, p_ln);
    // 2. qkv = xw @ qkv_w + b   [65536 x 576], K=192  (bf16 out)
    mma_gemm<1, true><<<dim3(5, 512), 256, GEMM_SMEM_BYTES>>>(p_ln, p_qkvwt, qkvb, nullptr, p_qkv, 576, 192);
    // 3. windowed attention (bf16)
    attn_mma_kernel<<<dim3(NHEADS, 256), 256, ATTN_SMEM_BYTES>>>(p_qkv, p_btab, p_attn);
    // 4. proj + inverse permute + residual -> x1 fp32
    mma_gemm<2, false><<<dim3(2, 512), 256, GEMM_SMEM_BYTES>>>(p_attn, p_projwt, projb, x, p_x1, 192, 192);
    // 5. LN2 (bf16 out)
    ln_kernel<false><<<NTOK / 8, 256>>>(p_x1, n2g, n2b, p_ln);
    // 6. r1 = hn @ fc1_A   [65536 x 384], K=192 (bf16)
    mma_gemm<0, true><<<dim3(3, 512), 256, GEMM_SMEM_BYTES>>>(p_ln, p_fc1At, nullptr, nullptr, p_r1, 384, 192);
    // 7. hid = r1 @ fc1_Bw + b   [65536 x 768], K=384 (bf16)
    mma_gemm<1, true><<<dim3(6, 512), 256, GEMM_SMEM_BYTES>>>(p_r1, p_fc1Bt, fc1Bb, nullptr, p_hid, 768, 384);
    // 8. tiled depthwise conv3d + bias + GELU (bf16)
    conv_gelu_tiled<<<dim3(6, 1024), 256, CONV_SMEM_BYTES>>>(p_hid, dww, dwb, p_conv);
    // 9. r2 = conv @ fc2_A   [65536 x 128(pad)], K=768 (bf16)
    mma_gemm<0, true><<<dim3(1, 512), 256, GEMM_SMEM_BYTES>>>(p_conv, p_fc2At, nullptr, nullptr, p_r2, 128, 768);
    // 10. out = x1 + r2 @ fc2_Bw + b   [65536 x 192], K=128(pad) (fp32)
    mma_gemm<3, false><<<dim3(2, 512), 256, GEMM_SMEM_BYTES>>>(p_r2, p_fc2Bt, fc2Bb, p_x1, out, 192, 128);
}

// round 15
// speedup vs baseline: 1.0107x; 1.0107x over previous
#include <cuda_runtime.h>
#include <cuda_bf16.h>
#include <math.h>

// Problem constants (B=1, D=16, H=64, W=64)
#define NTOK   65536
#define CDIM   192
#define NHEADS 6
#define HD     32
#define HIDDEN 768
#define RANK1  384
#define RANK2  96
#define ATTN_SCALE 0.17677669529663687f  // 32^-0.5

typedef __nv_bfloat16 bf16;

// ---------------- scratch (device globals; no runtime allocation) ----------------
__device__ bf16  g_ln[(size_t)NTOK * CDIM];
__device__ bf16  g_qkv[(size_t)NTOK * 576];
__device__ bf16  g_attn[(size_t)NTOK * CDIM];
__device__ float g_x1[(size_t)NTOK * CDIM];
__device__ bf16  g_r1[(size_t)NTOK * RANK1];
__device__ bf16  g_hid[(size_t)NTOK * HIDDEN];
__device__ bf16  g_conv[(size_t)NTOK * HIDDEN];
__device__ bf16  g_r2[(size_t)NTOK * 128];      // padded K (cols 96..127 = 0)
// transposed bf16 weights [N][K]
__device__ bf16  g_qkvwt[576 * 192];
__device__ bf16  g_projwt[192 * 192];
__device__ bf16  g_fc1At[RANK1 * 192];
__device__ bf16  g_fc1Bt[HIDDEN * RANK1];
__device__ bf16  g_fc2At[128 * HIDDEN];         // padded N rows 96..127 = 0
__device__ bf16  g_fc2Bt[CDIM * 128];           // padded K cols 96..127 = 0

// ---------------- helpers ----------------
__device__ __forceinline__ int token_to_wrow(int n) {
    int w = n & 63, h = (n >> 6) & 63, d = n >> 12;
    int win = ((d >> 2) << 6) | ((h >> 3) << 3) | (w >> 3);
    int t   = ((d & 3) << 6) | ((h & 7) << 3) | (w & 7);
    return (win << 8) | t;
}
__device__ __forceinline__ int wrow_to_token(int r) {
    int win = r >> 8, t = r & 255;
    int d = ((win >> 6) << 2) | (t >> 6);
    int h = (((win >> 3) & 7) << 3) | ((t >> 3) & 7);
    int w = ((win & 7) << 3) | (t & 7);
    return (d << 12) | (h << 6) | w;
}
__device__ __forceinline__ void cp16(void* smem, const void* gmem) {
    unsigned s = (unsigned)__cvta_generic_to_shared(smem);
    asm volatile("cp.async.cg.shared.global [%0], [%1], 16;\n" :: "r"(s), "l"(gmem));
}
__device__ __forceinline__ void cp16z(void* smem, const void* gmem) {
    unsigned s = (unsigned)__cvta_generic_to_shared(smem);
    asm volatile("cp.async.cg.shared.global [%0], [%1], 16, 0;\n" :: "r"(s), "l"(gmem));
}
__device__ __forceinline__ void ldsm4(unsigned* r, unsigned addr) {
    asm volatile("ldmatrix.sync.aligned.m8n8.x4.shared.b16 {%0,%1,%2,%3}, [%4];"
                 : "=r"(r[0]), "=r"(r[1]), "=r"(r[2]), "=r"(r[3]) : "r"(addr));
}
#define MMA_BF16(C, A, B)                                                      \
    asm volatile(                                                              \
        "mma.sync.aligned.m16n8k16.row.col.f32.bf16.bf16.f32 "                 \
        "{%0,%1,%2,%3},{%4,%5,%6,%7},{%8,%9},{%0,%1,%2,%3};\n"                 \
        : "+f"((C)[0]), "+f"((C)[1]), "+f"((C)[2]), "+f"((C)[3])               \
        : "r"((A)[0]), "r"((A)[1]), "r"((A)[2]), "r"((A)[3]),                  \
          "r"((B)[0]), "r"((B)[1]))

// ---------------- all-weights convert + transpose (one launch, with padding) -------
__global__ void wconv_all(const float* s0, const float* s1, const float* s2,
                          const float* s3, const float* s4, const float* s5,
                          bf16* d0, bf16* d1, bf16* d2,
                          bf16* d3, bf16* d4, bf16* d5) {
    int idx = blockIdx.x * 256 + threadIdx.x;
    if (idx < 110592) {                 // qkv [192][576] -> [576][192]
        int k = idx / 576, n = idx - k * 576;
        d0[n * 192 + k] = __float2bfloat16(s0[idx]);
    } else if (idx < 147456) {          // proj [192][192] -> [192][192]
        idx -= 110592;
        int k = idx / 192, n = idx - k * 192;
        d1[n * 192 + k] = __float2bfloat16(s1[idx]);
    } else if (idx < 221184) {          // fc1A [192][384] -> [384][192]
        idx -= 147456;
        int k = idx / 384, n = idx - k * 384;
        d2[n * 192 + k] = __float2bfloat16(s2[idx]);
    } else if (idx < 516096) {          // fc1B [384][768] -> [768][384]
        idx -= 221184;
        int k = idx / 768, n = idx - k * 768;
        d3[n * 384 + k] = __float2bfloat16(s3[idx]);
    } else if (idx < 614400) {          // fc2A [768][96] -> [128][768] (pad n)
        idx -= 516096;
        int n = idx / 768, k = idx - n * 768;
        d4[idx] = (n < 96) ? __float2bfloat16(s4[k * 96 + n]) : __float2bfloat16(0.f);
    } else if (idx < 638976) {          // fc2B [96][192] -> [192][128] (pad k)
        idx -= 614400;
        int n = idx / 128, k = idx - n * 128;
        d5[idx] = (k < 96) ? __float2bfloat16(s5[k * 192 + n]) : __float2bfloat16(0.f);
    }
}

// ---------------- LayerNorm: warp per token -> bf16 out ----------------
template <bool PERM>
__global__ void __launch_bounds__(256)
ln_kernel(const float* __restrict__ x, const float* __restrict__ g,
          const float* __restrict__ b, bf16* __restrict__ out) {
    int lane = threadIdx.x & 31, wid = threadIdx.x >> 5;
    int n = (blockIdx.x << 3) + wid;
    const float* xp = x + (size_t)n * CDIM;
    float v[6];
#pragma unroll
    for (int i = 0; i < 6; i++) v[i] = xp[lane + (i << 5)];
    float s = 0.f, s2 = 0.f;
#pragma unroll
    for (int i = 0; i < 6; i++) { s += v[i]; s2 += v[i] * v[i]; }
#pragma unroll
    for (int o = 16; o; o >>= 1) {
        s  += __shfl_xor_sync(0xffffffffu, s,  o);
        s2 += __shfl_xor_sync(0xffffffffu, s2, o);
    }
    float mean = s * (1.0f / CDIM);
    float rstd = rsqrtf(s2 * (1.0f / CDIM) - mean * mean + 1e-5f);
    int orow = PERM ? token_to_wrow(n) : n;
    bf16* op = out + (size_t)orow * CDIM;
#pragma unroll
    for (int i = 0; i < 6; i++) {
        int c = lane + (i << 5);
        op[c] = __float2bfloat16((v[i] - mean) * rstd * __ldg(g + c) + __ldg(b + c));
    }
}

// ---------------- BF16 GEMM 128x128x64, 2-stage, ldmatrix (R11 exact) --------------
#define GEMM_SMEM_BYTES (2 * 2 * 128 * 72 * 2)
#define ST_STRIDE (128 * 72)     // halves per stage per array
template <int MODE, bool OUTBF>
__global__ void __launch_bounds__(256)
mma_gemm(const bf16* __restrict__ A, const bf16* __restrict__ B,
         const float* __restrict__ bias, const float* __restrict__ resid,
         void* __restrict__ Cv, int N, int K) {
    extern __shared__ bf16 gsm[];
    bf16* As = gsm;                       // [2][128][72]
    bf16* Bs = gsm + 2 * ST_STRIDE;       // [2][128][72]
    int tid = threadIdx.x, lane = tid & 31, warp = tid >> 5;
    int wm = warp & 1, wn = warp >> 1;
    int bm = blockIdx.y << 7, bn = blockIdx.x << 7;
    int q = lane & 3, g8 = lane >> 2;

    float c[4][4][4];
#pragma unroll
    for (int mt = 0; mt < 4; mt++)
#pragma unroll
        for (int nt = 0; nt < 4; nt++)
#pragma unroll
            for (int r = 0; r < 4; r++) c[mt][nt][r] = 0.f;

    int KT = K >> 6;

    unsigned asm_base = (unsigned)__cvta_generic_to_shared(As);
    unsigned bsm_base = (unsigned)__cvta_generic_to_shared(Bs);
    int lrow = lane & 15, lcol = (lane >> 4) << 3;
    unsigned a_off = ((wm * 64 + lrow) * 72 + lcol) * 2;
    unsigned b_off = ((wn * 32 + lrow) * 72 + lcol) * 2;

#define COPY_STAGE(S, K0)                                                         \
    do {                                                                          \
        _Pragma("unroll")                                                         \
        for (int cc = 0; cc < 4; cc++) {                                          \
            int id = tid + (cc << 8);                                             \
            int r = id >> 3, o = (id & 7) << 3;                                   \
            cp16(&As[(S) * ST_STRIDE + r * 72 + o],                               \
                 A + (size_t)(bm + r) * K + (K0) + o);                            \
            if (bn + r < N)                                                       \
                cp16(&Bs[(S) * ST_STRIDE + r * 72 + o],                           \
                     B + (size_t)(bn + r) * K + (K0) + o);                        \
            else                                                                  \
                cp16z(&Bs[(S) * ST_STRIDE + r * 72 + o], B);                      \
        }                                                                         \
    } while (0)

    COPY_STAGE(0, 0);
    asm volatile("cp.async.commit_group;\n");

    for (int kt = 0; kt < KT; kt++) {
        asm volatile("cp.async.wait_group 0;\n");
        __syncthreads();
        if (kt + 1 < KT) COPY_STAGE((kt + 1) & 1, (kt + 1) << 6);
        asm volatile("cp.async.commit_group;\n");
        int s = kt & 1;
        unsigned aS = asm_base + s * (ST_STRIDE * 2) + a_off;
        unsigned bS = bsm_base + s * (ST_STRIDE * 2) + b_off;
#pragma unroll
        for (int kk = 0; kk < 64; kk += 16) {
            unsigned af[4][4], bf[4][4];
#pragma unroll
            for (int mt = 0; mt < 4; mt++)
                ldsm4(af[mt], aS + (mt * 16 * 72 + kk) * 2);
#pragma unroll
            for (int ntp = 0; ntp < 2; ntp++)
                ldsm4(bf[ntp * 2], bS + (ntp * 16 * 72 + kk) * 2);
#pragma unroll
            for (int mt = 0; mt < 4; mt++)
#pragma unroll
                for (int ntp = 0; ntp < 2; ntp++) {
                    unsigned b0[2] = { bf[ntp * 2][0], bf[ntp * 2][2] };
                    unsigned b1[2] = { bf[ntp * 2][1], bf[ntp * 2][3] };
                    MMA_BF16(c[mt][ntp * 2 + 0], af[mt], b0);
                    MMA_BF16(c[mt][ntp * 2 + 1], af[mt], b1);
                }
        }
    }
#undef COPY_STAGE

#pragma unroll
    for (int mt = 0; mt < 4; mt++) {
        int row0 = bm + wm * 64 + mt * 16 + g8;
#pragma unroll
        for (int half = 0; half < 2; half++) {
            int row = row0 + half * 8;
            int orow = (MODE == 2) ? wrow_to_token(row) : row;
#pragma unroll
            for (int nt = 0; nt < 4; nt++) {
                int col = bn + wn * 32 + nt * 8 + (q << 1);
                if (col < N) {
                    float v0 = c[mt][nt][half * 2 + 0];
                    float v1 = c[mt][nt][half * 2 + 1];
                    if (MODE >= 1) { v0 += bias[col]; v1 += bias[col + 1]; }
                    if (MODE >= 2) {
                        float2 rr = *(const float2*)(resid + (size_t)orow * N + col);
                        v0 += rr.x; v1 += rr.y;
                    }
                    if (OUTBF) {
                        *( __nv_bfloat162*)((bf16*)Cv + (size_t)orow * N + col) =
                            __floats2bfloat162_rn(v0, v1);
                    } else {
                        *(float2*)((float*)Cv + (size_t)orow * N + col) =
                            make_float2(v0, v1);
                    }
                }
            }
        }
    }
}

// ---------------- bf16 tensor-core windowed attention (smem bias, reduced ALU) -----
// smem: Ks 20480 | Vt 16896 | Ps 20480 | bsh 6304 | sid 1024 = 65184
#define ATTN_SMEM_BYTES 65184
__global__ void __launch_bounds__(256)
attn_mma_kernel(const bf16* __restrict__ qkv, const float* __restrict__ rel_bias,
                bf16* __restrict__ out) {
    extern __shared__ char smc[];
    bf16*  Ks  = (bf16*)smc;             // [256][40]
    bf16*  Vt  = (bf16*)(smc + 20480);   // [32][264]
    bf16*  Ps  = (bf16*)(smc + 37376);   // [256][40]  (Q staging, then P)
    float* bsh = (float*)(smc + 57856);  // [1575]
    int*   sid = (int*)(smc + 64160);    // [256]

    int head = blockIdx.x, win = blockIdx.y;
    int tid = threadIdx.x, lane = tid & 31, warp = tid >> 5;
    int q = lane & 3, g8 = lane >> 2;
    int m0 = warp << 5;

    const bf16* base = qkv + (size_t)win * 256 * 576 + head * HD;
    for (int idx = tid; idx < 256 * 32; idx += 256) {
        int r = idx >> 5, d = idx & 31;
        const bf16* p = base + (size_t)r * 576 + d;
        Ks[r * 40 + d]  = p[192];
        Vt[d * 264 + r] = p[384];
    }
#pragma unroll 4
    for (int i = 0; i < 32; i++)
        Ps[(m0 + i) * 40 + lane] = base[(size_t)(m0 + i) * 576 + lane];
    for (int i = tid; i < 1575; i += 256) bsh[i] = rel_bias[i * 6 + head];
    {
        int t = tid;
        int gd = ((win >> 6) << 2) | (t >> 6);
        int gh = (((win >> 3) & 7) << 3) | ((t >> 3) & 7);
        int gw = ((win & 7) << 3) | (t & 7);
        sid[t] = ((((gd + 2) & 15) >> 2) << 6) | ((((gh + 4) & 63) >> 3) << 3) |
                 (((gw + 4) & 63) >> 3);
    }
    __syncthreads();

    unsigned qf[2][2][4];
#pragma unroll
    for (int mt = 0; mt < 2; mt++)
#pragma unroll
        for (int ks = 0; ks < 2; ks++) {
            int m = m0 + mt * 16 + g8, k = ks * 16 + 2 * q;
            qf[mt][ks][0] = *(const unsigned*)&Ps[m * 40 + k];
            qf[mt][ks][1] = *(const unsigned*)&Ps[(m + 8) * 40 + k];
            qf[mt][ks][2] = *(const unsigned*)&Ps[m * 40 + k + 8];
            qf[mt][ks][3] = *(const unsigned*)&Ps[(m + 8) * 40 + k + 8];
        }
    // strength-reduced bias base: bidx = rbase[mt][h] - (cd*225 + ch*15) - e
    int rbase[2][2], msid[2][2];
#pragma unroll
    for (int mt = 0; mt < 2; mt++)
#pragma unroll
        for (int h = 0; h < 2; h++) {
            int r = m0 + mt * 16 + h * 8 + g8;
            rbase[mt][h] = (r >> 6) * 225 + ((r >> 3) & 7) * 15 + (r & 7)
                         + 787 - (q << 1);
            msid[mt][h] = sid[r];
        }
    __syncwarp();

    float o[2][4][4];
#pragma unroll
    for (int mt = 0; mt < 2; mt++)
#pragma unroll
        for (int nt = 0; nt < 4; nt++)
#pragma unroll
            for (int e = 0; e < 4; e++) o[mt][nt][e] = 0.f;
    float rs[2][2] = {{0.f, 0.f}, {0.f, 0.f}};

    for (int ck = 0; ck < 256; ck += 32) {
        float s[2][4][4];
#pragma unroll
        for (int mt = 0; mt < 2; mt++)
#pragma unroll
            for (int nt = 0; nt < 4; nt++)
#pragma unroll
                for (int e = 0; e < 4; e++) s[mt][nt][e] = 0.f;
#pragma unroll
        for (int ks = 0; ks < 2; ks++) {
            unsigned kf[4][2];
#pragma unroll
            for (int nt = 0; nt < 4; nt++) {
                int n = ck + nt * 8 + g8;
                kf[nt][0] = *(const unsigned*)&Ks[n * 40 + ks * 16 + 2 * q];
                kf[nt][1] = *(const unsigned*)&Ks[n * 40 + ks * 16 + 2 * q + 8];
            }
#pragma unroll
            for (int mt = 0; mt < 2; mt++)
#pragma unroll
                for (int nt = 0; nt < 4; nt++)
                    MMA_BF16(s[mt][nt], qf[mt][ks], kf[nt]);
        }
#pragma unroll
        for (int nt = 0; nt < 4; nt++) {
            int cc = ck + nt * 8;
            int coff = (cc >> 6) * 225 + ((cc >> 3) & 7) * 15;
            int sc = (q >= 2) ? sid[cc + 4] : sid[cc];
#pragma unroll
            for (int mt = 0; mt < 2; mt++)
#pragma unroll
                for (int h = 0; h < 2; h++) {
                    int bidx = rbase[mt][h] - coff;
                    float p0, p1;
                    if (msid[mt][h] == sc) {
                        p0 = __expf(fmaf(s[mt][nt][h * 2 + 0], ATTN_SCALE, bsh[bidx]));
                        p1 = __expf(fmaf(s[mt][nt][h * 2 + 1], ATTN_SCALE, bsh[bidx - 1]));
                    } else { p0 = 0.f; p1 = 0.f; }
                    __nv_bfloat162 pp = __floats2bfloat162_rn(p0, p1);
                    rs[mt][h] += __bfloat162float(pp.x) + __bfloat162float(pp.y);
                    int r = m0 + mt * 16 + h * 8 + g8;
                    *(__nv_bfloat162*)&Ps[r * 40 + nt * 8 + (q << 1)] = pp;
                }
        }
        __syncwarp();
#pragma unroll
        for (int ks = 0; ks < 2; ks++) {
            unsigned vf[4][2], pf[2][4];
#pragma unroll
            for (int nto = 0; nto < 4; nto++) {
                int d = nto * 8 + g8;
                vf[nto][0] = *(const unsigned*)&Vt[d * 264 + ck + ks * 16 + 2 * q];
                vf[nto][1] = *(const unsigned*)&Vt[d * 264 + ck + ks * 16 + 2 * q + 8];
            }
#pragma unroll
            for (int mt = 0; mt < 2; mt++) {
                int m = m0 + mt * 16 + g8, k = ks * 16 + 2 * q;
                pf[mt][0] = *(const unsigned*)&Ps[m * 40 + k];
                pf[mt][1] = *(const unsigned*)&Ps[(m + 8) * 40 + k];
                pf[mt][2] = *(const unsigned*)&Ps[m * 40 + k + 8];
                pf[mt][3] = *(const unsigned*)&Ps[(m + 8) * 40 + k + 8];
            }
#pragma unroll
            for (int mt = 0; mt < 2; mt++)
#pragma unroll
                for (int nto = 0; nto < 4; nto++)
                    MMA_BF16(o[mt][nto], pf[mt], vf[nto]);
        }
        __syncwarp();
    }

#pragma unroll
    for (int mt = 0; mt < 2; mt++)
#pragma unroll
        for (int h = 0; h < 2; h++) {
            float v = rs[mt][h];
            v += __shfl_xor_sync(0xffffffffu, v, 1);
            v += __shfl_xor_sync(0xffffffffu, v, 2);
            rs[mt][h] = 1.f / v;
        }
#pragma unroll
    for (int mt = 0; mt < 2; mt++)
#pragma unroll
        for (int h = 0; h < 2; h++) {
            int r = m0 + mt * 16 + h * 8 + g8;
            bf16* op = out + (size_t)(win * 256 + r) * CDIM + head * HD;
            float inv = rs[mt][h];
#pragma unroll
            for (int nto = 0; nto < 4; nto++)
                *(__nv_bfloat162*)(op + nto * 8 + (q << 1)) =
                    __floats2bfloat162_rn(o[mt][nto][h * 2 + 0] * inv,
                                          o[mt][nto][h * 2 + 1] * inv);
        }
}

// ---------------- tiled depthwise 3x3x3 conv + bias + exact GELU -------------------
// stencil register-reuse: per (td,th,kd,kh) load 6 halo values for 12 FMAs
#define CONV_SMEM_BYTES (216 * 128 * 2)
__global__ void __launch_bounds__(256)
conv_gelu_tiled(const bf16* __restrict__ hin, const float* __restrict__ wt,
                const float* __restrict__ cb, bf16* __restrict__ hout) {
    extern __shared__ bf16 hs[];   // [216][128]
    int cg = blockIdx.x;
    int tile = blockIdx.y;
    int d0 = (tile >> 8) << 2;
    int h0 = ((tile >> 4) & 15) << 2;
    int w0 = (tile & 15) << 2;
    int tid = threadIdx.x;
    int c = tid & 127;
    int phalf = tid >> 7;
    int cbase = cg << 7;

#pragma unroll 4
    for (int i = 0; i < 108; i++) {
        int p = phalf + (i << 1);
        int pd = p / 36, rem = p - pd * 36;
        int ph = rem / 6, pw = rem - ph * 6;
        int gd = d0 - 1 + pd, gh = h0 - 1 + ph, gw = w0 - 1 + pw;
        bf16 v = __float2bfloat16(0.f);
        if ((unsigned)gd < 16u && (unsigned)gh < 64u && (unsigned)gw < 64u)
            v = hin[(size_t)((gd << 12) | (gh << 6) | gw) * HIDDEN + cbase + c];
        hs[p * 128 + c] = v;
    }
    float w[27];
#pragma unroll
    for (int k = 0; k < 27; k++) w[k] = wt[(cbase + c) * 27 + k];
    float bias = cb[cbase + c];
    __syncthreads();

    int tdb = phalf << 1;   // this thread covers td in {tdb, tdb+1}
#pragma unroll
    for (int tdh = 0; tdh < 8; tdh++) {
        int td = tdb + (tdh >> 2), th = tdh & 3;
        float acc[4];
        acc[0] = acc[1] = acc[2] = acc[3] = bias;
#pragma unroll
        for (int kd = 0; kd < 3; kd++)
#pragma unroll
            for (int kh = 0; kh < 3; kh++) {
                int pbase = (td + kd) * 36 + (th + kh) * 6;
                float v[6];
#pragma unroll
                for (int j = 0; j < 6; j++)
                    v[j] = __bfloat162float(hs[(pbase + j) * 128 + c]);
                const float* wk = w + (kd * 3 + kh) * 3;
#pragma unroll
                for (int tw = 0; tw < 4; tw++)
                    acc[tw] += wk[0] * v[tw] + wk[1] * v[tw + 1] + wk[2] * v[tw + 2];
            }
        int nb = ((d0 + td) << 12) | ((h0 + th) << 6) | w0;
#pragma unroll
        for (int tw = 0; tw < 4; tw++) {
            float a = acc[tw];
            float gl = 0.5f * a * (1.f + erff(a * 0.70710678118654752f));
            hout[(size_t)(nb + tw) * HIDDEN + cbase + c] = __float2bfloat16(gl);
        }
    }
}

// ---------------- launch ----------------
extern "C" void kernel_launch(void* const* d_in, const int* in_sizes, int n_in,
                              void* d_out, int out_size) {
    const float* x     = (const float*)d_in[0];
    const float* n1g   = (const float*)d_in[1];
    const float* n1b   = (const float*)d_in[2];
    const float* qkvw  = (const float*)d_in[3];
    const float* qkvb  = (const float*)d_in[4];
    const float* relb  = (const float*)d_in[5];
    const float* projw = (const float*)d_in[6];
    const float* projb = (const float*)d_in[7];
    const float* n2g   = (const float*)d_in[8];
    const float* n2b   = (const float*)d_in[9];
    const float* fc1A  = (const float*)d_in[10];
    const float* fc1Bw = (const float*)d_in[11];
    const float* fc1Bb = (const float*)d_in[12];
    const float* dww   = (const float*)d_in[13];
    const float* dwb   = (const float*)d_in[14];
    const float* fc2A  = (const float*)d_in[15];
    const float* fc2Bw = (const float*)d_in[16];
    const float* fc2Bb = (const float*)d_in[17];
    float* out = (float*)d_out;

    bf16 *p_ln, *p_qkv, *p_attn, *p_r1, *p_hid, *p_conv, *p_r2;
    bf16 *p_qkvwt, *p_projwt, *p_fc1At, *p_fc1Bt, *p_fc2At, *p_fc2Bt;
    float *p_x1;
    cudaGetSymbolAddress((void**)&p_ln,    g_ln);
    cudaGetSymbolAddress((void**)&p_qkv,   g_qkv);
    cudaGetSymbolAddress((void**)&p_attn,  g_attn);
    cudaGetSymbolAddress((void**)&p_x1,    g_x1);
    cudaGetSymbolAddress((void**)&p_r1,    g_r1);
    cudaGetSymbolAddress((void**)&p_hid,   g_hid);
    cudaGetSymbolAddress((void**)&p_conv,  g_conv);
    cudaGetSymbolAddress((void**)&p_r2,    g_r2);
    cudaGetSymbolAddress((void**)&p_qkvwt, g_qkvwt);
    cudaGetSymbolAddress((void**)&p_projwt, g_projwt);
    cudaGetSymbolAddress((void**)&p_fc1At, g_fc1At);
    cudaGetSymbolAddress((void**)&p_fc1Bt, g_fc1Bt);
    cudaGetSymbolAddress((void**)&p_fc2At, g_fc2At);
    cudaGetSymbolAddress((void**)&p_fc2Bt, g_fc2Bt);

    cudaFuncSetAttribute(attn_mma_kernel, cudaFuncAttributeMaxDynamicSharedMemorySize,
                         ATTN_SMEM_BYTES);
    cudaFuncSetAttribute(conv_gelu_tiled, cudaFuncAttributeMaxDynamicSharedMemorySize,
                         CONV_SMEM_BYTES);
    cudaFuncSetAttribute(mma_gemm<0, true>,  cudaFuncAttributeMaxDynamicSharedMemorySize, GEMM_SMEM_BYTES);
    cudaFuncSetAttribute(mma_gemm<1, true>,  cudaFuncAttributeMaxDynamicSharedMemorySize, GEMM_SMEM_BYTES);
    cudaFuncSetAttribute(mma_gemm<2, false>, cudaFuncAttributeMaxDynamicSharedMemorySize, GEMM_SMEM_BYTES);
    cudaFuncSetAttribute(mma_gemm<3, false>, cudaFuncAttributeMaxDynamicSharedMemorySize, GEMM_SMEM_BYTES);

    // 0. all weights convert+transpose (one launch)
    wconv_all<<<(638976 + 255) / 256, 256>>>(qkvw, projw, fc1A, fc1Bw, fc2A, fc2Bw,
                                             p_qkvwt, p_projwt, p_fc1At, p_fc1Bt,
                                             p_fc2At, p_fc2Bt);

    // 1. LN1 + window permute (bf16 out)
    ln_kernel<true><<<NTOK / 8, 256>>>(x, n1g, n1b, p_ln);
    // 2. qkv = xw @ qkv_w + b   [65536 x 576], K=192  (bf16 out)
    mma_gemm<1, true><<<dim3(5, 512), 256, GEMM_SMEM_BYTES>>>(p_ln, p_qkvwt, qkvb, nullptr, p_qkv, 576, 192);
    // 3. windowed attention (bf16, smem bias)
    attn_mma_kernel<<<dim3(NHEADS, 256), 256, ATTN_SMEM_BYTES>>>(p_qkv, relb, p_attn);
    // 4. proj + inverse permute + residual -> x1 fp32
    mma_gemm<2, false><<<dim3(2, 512), 256, GEMM_SMEM_BYTES>>>(p_attn, p_projwt, projb, x, p_x1, 192, 192);
    // 5. LN2 (bf16 out)
    ln_kernel<false><<<NTOK / 8, 256>>>(p_x1, n2g, n2b, p_ln);
    // 6. r1 = hn @ fc1_A   [65536 x 384], K=192 (bf16)
    mma_gemm<0, true><<<dim3(3, 512), 256, GEMM_SMEM_BYTES>>>(p_ln, p_fc1At, nullptr, nullptr, p_r1, 384, 192);
    // 7. hid = r1 @ fc1_Bw + b   [65536 x 768], K=384 (bf16)
    mma_gemm<1, true><<<dim3(6, 512), 256, GEMM_SMEM_BYTES>>>(p_r1, p_fc1Bt, fc1Bb, nullptr, p_hid, 768, 384);
    // 8. tiled depthwise conv3d + bias + GELU (bf16)
    conv_gelu_tiled<<<dim3(6, 1024), 256, CONV_SMEM_BYTES>>>(p_hid, dww, dwb, p_conv);
    // 9. r2 = conv @ fc2_A   [65536 x 128(pad)], K=768 (bf16)
    mma_gemm<0, true><<<dim3(1, 512), 256, GEMM_SMEM_BYTES>>>(p_conv, p_fc2At, nullptr, nullptr, p_r2, 128, 768);
    // 10. out = x1 + r2 @ fc2_Bw + b   [65536 x 192], K=128(pad) (fp32)
    mma_gemm<3, false><<<dim3(2, 512), 256, GEMM_SMEM_BYTES>>>(p_r2, p_fc2Bt, fc2Bb, p_x1, out, 192, 128);
}

// round 16
// speedup vs baseline: 1.0184x; 1.0076x over previous
#include <cuda_runtime.h>
#include <cuda_bf16.h>
#include <math.h>

// Problem constants (B=1, D=16, H=64, W=64)
#define NTOK   65536
#define CDIM   192
#define NHEADS 6
#define HD     32
#define HIDDEN 768
#define RANK1  384
#define RANK2  96
#define ATTN_SCALE 0.17677669529663687f  // 32^-0.5

typedef __nv_bfloat16 bf16;

// ---------------- scratch (device globals; no runtime allocation) ----------------
__device__ bf16  g_ln[(size_t)NTOK * CDIM];
__device__ bf16  g_qkv[(size_t)NTOK * 576];
__device__ bf16  g_attn[(size_t)NTOK * CDIM];
__device__ float g_x1[(size_t)NTOK * CDIM];
__device__ bf16  g_r1[(size_t)NTOK * RANK1];
__device__ bf16  g_hid[(size_t)NTOK * HIDDEN];
__device__ bf16  g_conv[(size_t)NTOK * HIDDEN];
__device__ bf16  g_r2[(size_t)NTOK * 128];      // padded K (cols 96..127 = 0)
// transposed bf16 weights [N][K]
__device__ bf16  g_qkvwt[576 * 192];
__device__ bf16  g_projwt[192 * 192];
__device__ bf16  g_fc1At[RANK1 * 192];
__device__ bf16  g_fc1Bt[HIDDEN * RANK1];
__device__ bf16  g_fc2At[128 * HIDDEN];         // padded N rows 96..127 = 0
__device__ bf16  g_fc2Bt[CDIM * 128];           // padded K cols 96..127 = 0

// ---------------- helpers ----------------
__device__ __forceinline__ int token_to_wrow(int n) {
    int w = n & 63, h = (n >> 6) & 63, d = n >> 12;
    int win = ((d >> 2) << 6) | ((h >> 3) << 3) | (w >> 3);
    int t   = ((d & 3) << 6) | ((h & 7) << 3) | (w & 7);
    return (win << 8) | t;
}
__device__ __forceinline__ int wrow_to_token(int r) {
    int win = r >> 8, t = r & 255;
    int d = ((win >> 6) << 2) | (t >> 6);
    int h = (((win >> 3) & 7) << 3) | ((t >> 3) & 7);
    int w = ((win & 7) << 3) | (t & 7);
    return (d << 12) | (h << 6) | w;
}
__device__ __forceinline__ void cp16(void* smem, const void* gmem) {
    unsigned s = (unsigned)__cvta_generic_to_shared(smem);
    asm volatile("cp.async.cg.shared.global [%0], [%1], 16;\n" :: "r"(s), "l"(gmem));
}
__device__ __forceinline__ void cp16z(void* smem, const void* gmem) {
    unsigned s = (unsigned)__cvta_generic_to_shared(smem);
    asm volatile("cp.async.cg.shared.global [%0], [%1], 16, 0;\n" :: "r"(s), "l"(gmem));
}
__device__ __forceinline__ void ldsm4(unsigned* r, unsigned addr) {
    asm volatile("ldmatrix.sync.aligned.m8n8.x4.shared.b16 {%0,%1,%2,%3}, [%4];"
                 : "=r"(r[0]), "=r"(r[1]), "=r"(r[2]), "=r"(r[3]) : "r"(addr));
}
#define MMA_BF16(C, A, B)                                                      \
    asm volatile(                                                              \
        "mma.sync.aligned.m16n8k16.row.col.f32.bf16.bf16.f32 "                 \
        "{%0,%1,%2,%3},{%4,%5,%6,%7},{%8,%9},{%0,%1,%2,%3};\n"                 \
        : "+f"((C)[0]), "+f"((C)[1]), "+f"((C)[2]), "+f"((C)[3])               \
        : "r"((A)[0]), "r"((A)[1]), "r"((A)[2]), "r"((A)[3]),                  \
          "r"((B)[0]), "r"((B)[1]))

// ---------------- all-weights convert + transpose (one launch, with padding) -------
__global__ void wconv_all(const float* s0, const float* s1, const float* s2,
                          const float* s3, const float* s4, const float* s5,
                          bf16* d0, bf16* d1, bf16* d2,
                          bf16* d3, bf16* d4, bf16* d5) {
    int idx = blockIdx.x * 256 + threadIdx.x;
    if (idx < 110592) {                 // qkv [192][576] -> [576][192]
        int k = idx / 576, n = idx - k * 576;
        d0[n * 192 + k] = __float2bfloat16(s0[idx]);
    } else if (idx < 147456) {          // proj [192][192] -> [192][192]
        idx -= 110592;
        int k = idx / 192, n = idx - k * 192;
        d1[n * 192 + k] = __float2bfloat16(s1[idx]);
    } else if (idx < 221184) {          // fc1A [192][384] -> [384][192]
        idx -= 147456;
        int k = idx / 384, n = idx - k * 384;
        d2[n * 192 + k] = __float2bfloat16(s2[idx]);
    } else if (idx < 516096) {          // fc1B [384][768] -> [768][384]
        idx -= 221184;
        int k = idx / 768, n = idx - k * 768;
        d3[n * 384 + k] = __float2bfloat16(s3[idx]);
    } else if (idx < 614400) {          // fc2A [768][96] -> [128][768] (pad n)
        idx -= 516096;
        int n = idx / 768, k = idx - n * 768;
        d4[idx] = (n < 96) ? __float2bfloat16(s4[k * 96 + n]) : __float2bfloat16(0.f);
    } else if (idx < 638976) {          // fc2B [96][192] -> [192][128] (pad k)
        idx -= 614400;
        int n = idx / 128, k = idx - n * 128;
        d5[idx] = (k < 96) ? __float2bfloat16(s5[k * 192 + n]) : __float2bfloat16(0.f);
    }
}

// ---------------- LayerNorm: warp per token -> bf16 out ----------------
template <bool PERM>
__global__ void __launch_bounds__(256)
ln_kernel(const float* __restrict__ x, const float* __restrict__ g,
          const float* __restrict__ b, bf16* __restrict__ out) {
    int lane = threadIdx.x & 31, wid = threadIdx.x >> 5;
    int n = (blockIdx.x << 3) + wid;
    const float* xp = x + (size_t)n * CDIM;
    float v[6];
#pragma unroll
    for (int i = 0; i < 6; i++) v[i] = xp[lane + (i << 5)];
    float s = 0.f, s2 = 0.f;
#pragma unroll
    for (int i = 0; i < 6; i++) { s += v[i]; s2 += v[i] * v[i]; }
#pragma unroll
    for (int o = 16; o; o >>= 1) {
        s  += __shfl_xor_sync(0xffffffffu, s,  o);
        s2 += __shfl_xor_sync(0xffffffffu, s2, o);
    }
    float mean = s * (1.0f / CDIM);
    float rstd = rsqrtf(s2 * (1.0f / CDIM) - mean * mean + 1e-5f);
    int orow = PERM ? token_to_wrow(n) : n;
    bf16* op = out + (size_t)orow * CDIM;
#pragma unroll
    for (int i = 0; i < 6; i++) {
        int c = lane + (i << 5);
        op[c] = __float2bfloat16((v[i] - mean) * rstd * __ldg(g + c) + __ldg(b + c));
    }
}

// ---------------- BF16 GEMM 128x128x64, 2-stage, ldmatrix (R11 exact) --------------
#define GEMM_SMEM_BYTES (2 * 2 * 128 * 72 * 2)
#define ST_STRIDE (128 * 72)     // halves per stage per array
template <int MODE, bool OUTBF>
__global__ void __launch_bounds__(256)
mma_gemm(const bf16* __restrict__ A, const bf16* __restrict__ B,
         const float* __restrict__ bias, const float* __restrict__ resid,
         void* __restrict__ Cv, int N, int K) {
    extern __shared__ bf16 gsm[];
    bf16* As = gsm;                       // [2][128][72]
    bf16* Bs = gsm + 2 * ST_STRIDE;       // [2][128][72]
    int tid = threadIdx.x, lane = tid & 31, warp = tid >> 5;
    int wm = warp & 1, wn = warp >> 1;
    int bm = blockIdx.y << 7, bn = blockIdx.x << 7;
    int q = lane & 3, g8 = lane >> 2;

    float c[4][4][4];
#pragma unroll
    for (int mt = 0; mt < 4; mt++)
#pragma unroll
        for (int nt = 0; nt < 4; nt++)
#pragma unroll
            for (int r = 0; r < 4; r++) c[mt][nt][r] = 0.f;

    int KT = K >> 6;

    unsigned asm_base = (unsigned)__cvta_generic_to_shared(As);
    unsigned bsm_base = (unsigned)__cvta_generic_to_shared(Bs);
    int lrow = lane & 15, lcol = (lane >> 4) << 3;
    unsigned a_off = ((wm * 64 + lrow) * 72 + lcol) * 2;
    unsigned b_off = ((wn * 32 + lrow) * 72 + lcol) * 2;

#define COPY_STAGE(S, K0)                                                         \
    do {                                                                          \
        _Pragma("unroll")                                                         \
        for (int cc = 0; cc < 4; cc++) {                                          \
            int id = tid + (cc << 8);                                             \
            int r = id >> 3, o = (id & 7) << 3;                                   \
            cp16(&As[(S) * ST_STRIDE + r * 72 + o],                               \
                 A + (size_t)(bm + r) * K + (K0) + o);                            \
            if (bn + r < N)                                                       \
                cp16(&Bs[(S) * ST_STRIDE + r * 72 + o],                           \
                     B + (size_t)(bn + r) * K + (K0) + o);                        \
            else                                                                  \
                cp16z(&Bs[(S) * ST_STRIDE + r * 72 + o], B);                      \
        }                                                                         \
    } while (0)

    COPY_STAGE(0, 0);
    asm volatile("cp.async.commit_group;\n");

    for (int kt = 0; kt < KT; kt++) {
        asm volatile("cp.async.wait_group 0;\n");
        __syncthreads();
        if (kt + 1 < KT) COPY_STAGE((kt + 1) & 1, (kt + 1) << 6);
        asm volatile("cp.async.commit_group;\n");
        int s = kt & 1;
        unsigned aS = asm_base + s * (ST_STRIDE * 2) + a_off;
        unsigned bS = bsm_base + s * (ST_STRIDE * 2) + b_off;
#pragma unroll
        for (int kk = 0; kk < 64; kk += 16) {
            unsigned af[4][4], bf[4][4];
#pragma unroll
            for (int mt = 0; mt < 4; mt++)
                ldsm4(af[mt], aS + (mt * 16 * 72 + kk) * 2);
#pragma unroll
            for (int ntp = 0; ntp < 2; ntp++)
                ldsm4(bf[ntp * 2], bS + (ntp * 16 * 72 + kk) * 2);
#pragma unroll
            for (int mt = 0; mt < 4; mt++)
#pragma unroll
                for (int ntp = 0; ntp < 2; ntp++) {
                    unsigned b0[2] = { bf[ntp * 2][0], bf[ntp * 2][2] };
                    unsigned b1[2] = { bf[ntp * 2][1], bf[ntp * 2][3] };
                    MMA_BF16(c[mt][ntp * 2 + 0], af[mt], b0);
                    MMA_BF16(c[mt][ntp * 2 + 1], af[mt], b1);
                }
        }
    }
#undef COPY_STAGE

#pragma unroll
    for (int mt = 0; mt < 4; mt++) {
        int row0 = bm + wm * 64 + mt * 16 + g8;
#pragma unroll
        for (int half = 0; half < 2; half++) {
            int row = row0 + half * 8;
            int orow = (MODE == 2) ? wrow_to_token(row) : row;
#pragma unroll
            for (int nt = 0; nt < 4; nt++) {
                int col = bn + wn * 32 + nt * 8 + (q << 1);
                if (col < N) {
                    float v0 = c[mt][nt][half * 2 + 0];
                    float v1 = c[mt][nt][half * 2 + 1];
                    if (MODE >= 1) { v0 += bias[col]; v1 += bias[col + 1]; }
                    if (MODE >= 2) {
                        float2 rr = *(const float2*)(resid + (size_t)orow * N + col);
                        v0 += rr.x; v1 += rr.y;
                    }
                    if (OUTBF) {
                        *( __nv_bfloat162*)((bf16*)Cv + (size_t)orow * N + col) =
                            __floats2bfloat162_rn(v0, v1);
                    } else {
                        *(float2*)((float*)Cv + (size_t)orow * N + col) =
                            make_float2(v0, v1);
                    }
                }
            }
        }
    }
}

// ---------------- bf16 tensor-core windowed attention (smem bias, reduced ALU) -----
// smem: Ks 20480 | Vt 16896 | Ps 20480 | bsh 6304 | sid 1024 = 65184
#define ATTN_SMEM_BYTES 65184
__global__ void __launch_bounds__(256)
attn_mma_kernel(const bf16* __restrict__ qkv, const float* __restrict__ rel_bias,
                bf16* __restrict__ out) {
    extern __shared__ char smc[];
    bf16*  Ks  = (bf16*)smc;             // [256][40]
    bf16*  Vt  = (bf16*)(smc + 20480);   // [32][264]
    bf16*  Ps  = (bf16*)(smc + 37376);   // [256][40]  (Q staging, then P)
    float* bsh = (float*)(smc + 57856);  // [1575]
    int*   sid = (int*)(smc + 64160);    // [256]

    int head = blockIdx.x, win = blockIdx.y;
    int tid = threadIdx.x, lane = tid & 31, warp = tid >> 5;
    int q = lane & 3, g8 = lane >> 2;
    int m0 = warp << 5;

    const bf16* base = qkv + (size_t)win * 256 * 576 + head * HD;
    for (int idx = tid; idx < 256 * 32; idx += 256) {
        int r = idx >> 5, d = idx & 31;
        const bf16* p = base + (size_t)r * 576 + d;
        Ks[r * 40 + d]  = p[192];
        Vt[d * 264 + r] = p[384];
    }
#pragma unroll 4
    for (int i = 0; i < 32; i++)
        Ps[(m0 + i) * 40 + lane] = base[(size_t)(m0 + i) * 576 + lane];
    for (int i = tid; i < 1575; i += 256) bsh[i] = rel_bias[i * 6 + head];
    {
        int t = tid;
        int gd = ((win >> 6) << 2) | (t >> 6);
        int gh = (((win >> 3) & 7) << 3) | ((t >> 3) & 7);
        int gw = ((win & 7) << 3) | (t & 7);
        sid[t] = ((((gd + 2) & 15) >> 2) << 6) | ((((gh + 4) & 63) >> 3) << 3) |
                 (((gw + 4) & 63) >> 3);
    }
    __syncthreads();

    unsigned qf[2][2][4];
#pragma unroll
    for (int mt = 0; mt < 2; mt++)
#pragma unroll
        for (int ks = 0; ks < 2; ks++) {
            int m = m0 + mt * 16 + g8, k = ks * 16 + 2 * q;
            qf[mt][ks][0] = *(const unsigned*)&Ps[m * 40 + k];
            qf[mt][ks][1] = *(const unsigned*)&Ps[(m + 8) * 40 + k];
            qf[mt][ks][2] = *(const unsigned*)&Ps[m * 40 + k + 8];
            qf[mt][ks][3] = *(const unsigned*)&Ps[(m + 8) * 40 + k + 8];
        }
    // strength-reduced bias base: bidx = rbase[mt][h] - (cd*225 + ch*15) - e
    int rbase[2][2], msid[2][2];
#pragma unroll
    for (int mt = 0; mt < 2; mt++)
#pragma unroll
        for (int h = 0; h < 2; h++) {
            int r = m0 + mt * 16 + h * 8 + g8;
            rbase[mt][h] = (r >> 6) * 225 + ((r >> 3) & 7) * 15 + (r & 7)
                         + 787 - (q << 1);
            msid[mt][h] = sid[r];
        }
    __syncwarp();

    float o[2][4][4];
#pragma unroll
    for (int mt = 0; mt < 2; mt++)
#pragma unroll
        for (int nt = 0; nt < 4; nt++)
#pragma unroll
            for (int e = 0; e < 4; e++) o[mt][nt][e] = 0.f;
    float rs[2][2] = {{0.f, 0.f}, {0.f, 0.f}};

    for (int ck = 0; ck < 256; ck += 32) {
        float s[2][4][4];
#pragma unroll
        for (int mt = 0; mt < 2; mt++)
#pragma unroll
            for (int nt = 0; nt < 4; nt++)
#pragma unroll
                for (int e = 0; e < 4; e++) s[mt][nt][e] = 0.f;
#pragma unroll
        for (int ks = 0; ks < 2; ks++) {
            unsigned kf[4][2];
#pragma unroll
            for (int nt = 0; nt < 4; nt++) {
                int n = ck + nt * 8 + g8;
                kf[nt][0] = *(const unsigned*)&Ks[n * 40 + ks * 16 + 2 * q];
                kf[nt][1] = *(const unsigned*)&Ks[n * 40 + ks * 16 + 2 * q + 8];
            }
#pragma unroll
            for (int mt = 0; mt < 2; mt++)
#pragma unroll
                for (int nt = 0; nt < 4; nt++)
                    MMA_BF16(s[mt][nt], qf[mt][ks], kf[nt]);
        }
#pragma unroll
        for (int nt = 0; nt < 4; nt++) {
            int cc = ck + nt * 8;
            int coff = (cc >> 6) * 225 + ((cc >> 3) & 7) * 15;
            int sc = (q >= 2) ? sid[cc + 4] : sid[cc];
#pragma unroll
            for (int mt = 0; mt < 2; mt++)
#pragma unroll
                for (int h = 0; h < 2; h++) {
                    int bidx = rbase[mt][h] - coff;
                    float p0, p1;
                    if (msid[mt][h] == sc) {
                        p0 = __expf(fmaf(s[mt][nt][h * 2 + 0], ATTN_SCALE, bsh[bidx]));
                        p1 = __expf(fmaf(s[mt][nt][h * 2 + 1], ATTN_SCALE, bsh[bidx - 1]));
                    } else { p0 = 0.f; p1 = 0.f; }
                    __nv_bfloat162 pp = __floats2bfloat162_rn(p0, p1);
                    rs[mt][h] += __bfloat162float(pp.x) + __bfloat162float(pp.y);
                    int r = m0 + mt * 16 + h * 8 + g8;
                    *(__nv_bfloat162*)&Ps[r * 40 + nt * 8 + (q << 1)] = pp;
                }
        }
        __syncwarp();
#pragma unroll
        for (int ks = 0; ks < 2; ks++) {
            unsigned vf[4][2], pf[2][4];
#pragma unroll
            for (int nto = 0; nto < 4; nto++) {
                int d = nto * 8 + g8;
                vf[nto][0] = *(const unsigned*)&Vt[d * 264 + ck + ks * 16 + 2 * q];
                vf[nto][1] = *(const unsigned*)&Vt[d * 264 + ck + ks * 16 + 2 * q + 8];
            }
#pragma unroll
            for (int mt = 0; mt < 2; mt++) {
                int m = m0 + mt * 16 + g8, k = ks * 16 + 2 * q;
                pf[mt][0] = *(const unsigned*)&Ps[m * 40 + k];
                pf[mt][1] = *(const unsigned*)&Ps[(m + 8) * 40 + k];
                pf[mt][2] = *(const unsigned*)&Ps[m * 40 + k + 8];
                pf[mt][3] = *(const unsigned*)&Ps[(m + 8) * 40 + k + 8];
            }
#pragma unroll
            for (int mt = 0; mt < 2; mt++)
#pragma unroll
                for (int nto = 0; nto < 4; nto++)
                    MMA_BF16(o[mt][nto], pf[mt], vf[nto]);
        }
        __syncwarp();
    }

#pragma unroll
    for (int mt = 0; mt < 2; mt++)
#pragma unroll
        for (int h = 0; h < 2; h++) {
            float v = rs[mt][h];
            v += __shfl_xor_sync(0xffffffffu, v, 1);
            v += __shfl_xor_sync(0xffffffffu, v, 2);
            rs[mt][h] = 1.f / v;
        }
#pragma unroll
    for (int mt = 0; mt < 2; mt++)
#pragma unroll
        for (int h = 0; h < 2; h++) {
            int r = m0 + mt * 16 + h * 8 + g8;
            bf16* op = out + (size_t)(win * 256 + r) * CDIM + head * HD;
            float inv = rs[mt][h];
#pragma unroll
            for (int nto = 0; nto < 4; nto++)
                *(__nv_bfloat162*)(op + nto * 8 + (q << 1)) =
                    __floats2bfloat162_rn(o[mt][nto][h * 2 + 0] * inv,
                                          o[mt][nto][h * 2 + 1] * inv);
        }
}

// ---------------- tiled depthwise 3x3x3 conv + bias + exact GELU -------------------
// stencil register-reuse: per (td,th,kd,kh) load 6 halo values for 12 FMAs
#define CONV_SMEM_BYTES (216 * 128 * 2)
__global__ void __launch_bounds__(256)
conv_gelu_tiled(const bf16* __restrict__ hin, const float* __restrict__ wt,
                const float* __restrict__ cb, bf16* __restrict__ hout) {
    extern __shared__ bf16 hs[];   // [216][128]
    int cg = blockIdx.x;
    int tile = blockIdx.y;
    int d0 = (tile >> 8) << 2;
    int h0 = ((tile >> 4) & 15) << 2;
    int w0 = (tile & 15) << 2;
    int tid = threadIdx.x;
    int c = tid & 127;
    int phalf = tid >> 7;
    int cbase = cg << 7;

#pragma unroll 4
    for (int i = 0; i < 108; i++) {
        int p = phalf + (i << 1);
        int pd = p / 36, rem = p - pd * 36;
        int ph = rem / 6, pw = rem - ph * 6;
        int gd = d0 - 1 + pd, gh = h0 - 1 + ph, gw = w0 - 1 + pw;
        bf16 v = __float2bfloat16(0.f);
        if ((unsigned)gd < 16u && (unsigned)gh < 64u && (unsigned)gw < 64u)
            v = hin[(size_t)((gd << 12) | (gh << 6) | gw) * HIDDEN + cbase + c];
        hs[p * 128 + c] = v;
    }
    float w[27];
#pragma unroll
    for (int k = 0; k < 27; k++) w[k] = wt[(cbase + c) * 27 + k];
    float bias = cb[cbase + c];
    __syncthreads();

    int tdb = phalf << 1;   // this thread covers td in {tdb, tdb+1}
#pragma unroll
    for (int tdh = 0; tdh < 8; tdh++) {
        int td = tdb + (tdh >> 2), th = tdh & 3;
        float acc[4];
        acc[0] = acc[1] = acc[2] = acc[3] = bias;
#pragma unroll
        for (int kd = 0; kd < 3; kd++)
#pragma unroll
            for (int kh = 0; kh < 3; kh++) {
                int pbase = (td + kd) * 36 + (th + kh) * 6;
                float v[6];
#pragma unroll
                for (int j = 0; j < 6; j++)
                    v[j] = __bfloat162float(hs[(pbase + j) * 128 + c]);
                const float* wk = w + (kd * 3 + kh) * 3;
#pragma unroll
                for (int tw = 0; tw < 4; tw++)
                    acc[tw] += wk[0] * v[tw] + wk[1] * v[tw + 1] + wk[2] * v[tw + 2];
            }
        int nb = ((d0 + td) << 12) | ((h0 + th) << 6) | w0;
#pragma unroll
        for (int tw = 0; tw < 4; tw++) {
            float a = acc[tw];
            float gl = 0.5f * a * (1.f + erff(a * 0.70710678118654752f));
            hout[(size_t)(nb + tw) * HIDDEN + cbase + c] = __float2bfloat16(gl);
        }
    }
}

// ---------------- launch ----------------
extern "C" void kernel_launch(void* const* d_in, const int* in_sizes, int n_in,
                              void* d_out, int out_size) {
    const float* x     = (const float*)d_in[0];
    const float* n1g   = (const float*)d_in[1];
    const float* n1b   = (const float*)d_in[2];
    const float* qkvw  = (const float*)d_in[3];
    const float* qkvb  = (const float*)d_in[4];
    const float* relb  = (const float*)d_in[5];
    const float* projw = (const float*)d_in[6];
    const float* projb = (const float*)d_in[7];
    const float* n2g   = (const float*)d_in[8];
    const float* n2b   = (const float*)d_in[9];
    const float* fc1A  = (const float*)d_in[10];
    const float* fc1Bw = (const float*)d_in[11];
    const float* fc1Bb = (const float*)d_in[12];
    const float* dww   = (const float*)d_in[13];
    const float* dwb   = (const float*)d_in[14];
    const float* fc2A  = (const float*)d_in[15];
    const float* fc2Bw = (const float*)d_in[16];
    const float* fc2Bb = (const float*)d_in[17];
    float* out = (float*)d_out;

    bf16 *p_ln, *p_qkv, *p_attn, *p_r1, *p_hid, *p_conv, *p_r2;
    bf16 *p_qkvwt, *p_projwt, *p_fc1At, *p_fc1Bt, *p_fc2At, *p_fc2Bt;
    float *p_x1;
    cudaGetSymbolAddress((void**)&p_ln,    g_ln);
    cudaGetSymbolAddress((void**)&p_qkv,   g_qkv);
    cudaGetSymbolAddress((void**)&p_attn,  g_attn);
    cudaGetSymbolAddress((void**)&p_x1,    g_x1);
    cudaGetSymbolAddress((void**)&p_r1,    g_r1);
    cudaGetSymbolAddress((void**)&p_hid,   g_hid);
    cudaGetSymbolAddress((void**)&p_conv,  g_conv);
    cudaGetSymbolAddress((void**)&p_r2,    g_r2);
    cudaGetSymbolAddress((void**)&p_qkvwt, g_qkvwt);
    cudaGetSymbolAddress((void**)&p_projwt, g_projwt);
    cudaGetSymbolAddress((void**)&p_fc1At, g_fc1At);
    cudaGetSymbolAddress((void**)&p_fc1Bt, g_fc1Bt);
    cudaGetSymbolAddress((void**)&p_fc2At, g_fc2At);
    cudaGetSymbolAddress((void**)&p_fc2Bt, g_fc2Bt);

    cudaFuncSetAttribute(attn_mma_kernel, cudaFuncAttributeMaxDynamicSharedMemorySize,
                         ATTN_SMEM_BYTES);
    cudaFuncSetAttribute(conv_gelu_tiled, cudaFuncAttributeMaxDynamicSharedMemorySize,
                         CONV_SMEM_BYTES);
    cudaFuncSetAttribute(mma_gemm<0, true>,  cudaFuncAttributeMaxDynamicSharedMemorySize, GEMM_SMEM_BYTES);
    cudaFuncSetAttribute(mma_gemm<1, true>,  cudaFuncAttributeMaxDynamicSharedMemorySize, GEMM_SMEM_BYTES);
    cudaFuncSetAttribute(mma_gemm<2, false>, cudaFuncAttributeMaxDynamicSharedMemorySize, GEMM_SMEM_BYTES);
    cudaFuncSetAttribute(mma_gemm<3, false>, cudaFuncAttributeMaxDynamicSharedMemorySize, GEMM_SMEM_BYTES);

    // 0. all weights convert+transpose (one launch)
    wconv_all<<<(638976 + 255) / 256, 256>>>(qkvw, projw, fc1A, fc1Bw, fc2A, fc2Bw,
                                             p_qkvwt, p_projwt, p_fc1At, p_fc1Bt,
                                             p_fc2At, p_fc2Bt);

    // 1. LN1 + window permute (bf16 out)
    ln_kernel<true><<<NTOK / 8, 256>>>(x, n1g, n1b, p_ln);
    // 2. qkv = xw @ qkv_w + b   [65536 x 576], K=192  (bf16 out)
    mma_gemm<1, true><<<dim3(5, 512), 256, GEMM_SMEM_BYTES>>>(p_ln, p_qkvwt, qkvb, nullptr, p_qkv, 576, 192);
    // 3. windowed attention (bf16, smem bias)
    attn_mma_kernel<<<dim3(NHEADS, 256), 256, ATTN_SMEM_BYTES>>>(p_qkv, relb, p_attn);
    // 4. proj + inverse permute + residual -> x1 fp32
    mma_gemm<2, false><<<dim3(2, 512), 256, GEMM_SMEM_BYTES>>>(p_attn, p_projwt, projb, x, p_x1, 192, 192);
    // 5. LN2 (bf16 out)
    ln_kernel<false><<<NTOK / 8, 256>>>(p_x1, n2g, n2b, p_ln);
    // 6. r1 = hn @ fc1_A   [65536 x 384], K=192 (bf16)
    mma_gemm<0, true><<<dim3(3, 512), 256, GEMM_SMEM_BYTES>>>(p_ln, p_fc1At, nullptr, nullptr, p_r1, 384, 192);
    // 7. hid = r1 @ fc1_Bw + b   [65536 x 768], K=384 (bf16)
    mma_gemm<1, true><<<dim3(6, 512), 256, GEMM_SMEM_BYTES>>>(p_r1, p_fc1Bt, fc1Bb, nullptr, p_hid, 768, 384);
    // 8. tiled depthwise conv3d + bias + GELU (bf16)
    conv_gelu_tiled<<<dim3(6, 1024), 256, CONV_SMEM_BYTES>>>(p_hid, dww, dwb, p_conv);
    // 9. r2 = conv @ fc2_A   [65536 x 128(pad)], K=768 (bf16)
    mma_gemm<0, true><<<dim3(1, 512), 256, GEMM_SMEM_BYTES>>>(p_conv, p_fc2At, nullptr, nullptr, p_r2, 128, 768);
    // 10. out = x1 + r2 @ fc2_Bw + b   [65536 x 192], K=128(pad) (fp32)
    mma_gemm<3, false><<<dim3(2, 512), 256, GEMM_SMEM_BYTES>>>(p_r2, p_fc2Bt, fc2Bb, p_x1, out, 192, 128);
}